// round 7
// baseline (speedup 1.0000x reference)
#include <cuda_runtime.h>
#include <cuda_bf16.h>
#include <math.h>
#include <stdint.h>

#define DIM    2048
#define BATCH  16384
#define NLAYERS 4

static __device__ __constant__ float kS[3] = {0.1f, 0.1f, 0.05f};
#define DIVC 0.38f
#define CAPV 10.0f

// tcgen05 is an arch-accelerated feature: only emit its PTX in the sm_10Xa pass.
#if defined(__CUDA_ARCH_FEAT_SM103_ALL) || defined(__CUDA_ARCH_FEAT_SM100_ALL) || defined(__CUDA_ARCH_FEAT_SM101_ALL)
#define HAS_TCGEN05 1
#else
#define HAS_TCGEN05 0
#endif

// ---------------- scratch (static device globals; no allocation) -------------
__device__ __nv_bfloat16 g_hhi[(size_t)BATCH * DIM];
__device__ __nv_bfloat16 g_hlo[(size_t)BATCH * DIM];
__device__ __nv_bfloat16 g_Thi[(size_t)BATCH * DIM];
__device__ __nv_bfloat16 g_Tlo[(size_t)BATCH * DIM];
__device__ __nv_bfloat16 g_W1hi[(size_t)DIM * DIM];
__device__ __nv_bfloat16 g_W1lo[(size_t)DIM * DIM];
__device__ __nv_bfloat16 g_W2hi[(size_t)DIM * DIM];
__device__ __nv_bfloat16 g_W2lo[(size_t)DIM * DIM];
__device__ float g_D[(size_t)BATCH * DIM];
__device__ float g_dirs[3 * DIM];
__device__ float g_coef[(size_t)BATCH * 4];

// ---------------- PTX helpers -------------------------------------------------
__device__ __forceinline__ uint32_t smem_u32(const void* p) {
    uint32_t a;
    asm("{ .reg .u64 t; cvta.to.shared.u64 t, %1; cvt.u32.u64 %0, t; }" : "=r"(a) : "l"(p));
    return a;
}
__device__ __forceinline__ uint32_t elect_one() {
    uint32_t p;
    asm volatile("{\n\t.reg .pred p;\n\telect.sync _|p, 0xFFFFFFFF;\n\tselp.b32 %0, 1, 0, p;\n\t}" : "=r"(p));
    return p;
}

#if HAS_TCGEN05
#define TCGEN05_ALLOC(sm, n) \
    asm volatile("tcgen05.alloc.cta_group::1.sync.aligned.shared::cta.b32 [%0], %1;" :: "r"(sm), "r"(n) : "memory")
#define TCGEN05_RELINQ() \
    asm volatile("tcgen05.relinquish_alloc_permit.cta_group::1.sync.aligned;")
#define TCGEN05_DEALLOC(t, n) \
    asm volatile("tcgen05.dealloc.cta_group::1.sync.aligned.b32 %0, %1;" :: "r"(t), "r"(n))
#define TCGEN05_COMMIT(mb) \
    asm volatile("tcgen05.commit.cta_group::1.mbarrier::arrive::one.shared::cluster.b64 [%0];" :: "r"(mb) : "memory")
#define TCGEN05_FENCE_AFTER() asm volatile("tcgen05.fence::after_thread_sync;" ::: "memory")
#define TCGEN05_WAIT_LD() asm volatile("tcgen05.wait::ld.sync.aligned;" ::: "memory")
#else
#define TCGEN05_ALLOC(sm, n)   ((void)0)
#define TCGEN05_RELINQ()       ((void)0)
#define TCGEN05_DEALLOC(t, n)  ((void)0)
#define TCGEN05_COMMIT(mb)     ((void)0)
#define TCGEN05_FENCE_AFTER()  ((void)0)
#define TCGEN05_WAIT_LD()      ((void)0)
#endif

#define MBARRIER_INIT(mb, c) \
    asm volatile("mbarrier.init.shared.b64 [%0], %1;" :: "r"(mb), "r"(c) : "memory")
#define MBARRIER_INVAL(mb) \
    asm volatile("mbarrier.inval.shared.b64 [%0];" :: "r"(mb) : "memory")
#define FENCE_PROXY_ASYNC() asm volatile("fence.proxy.async.shared::cta;" ::: "memory")
#define CP_ASYNC16(dst, src) \
    asm volatile("cp.async.cg.shared.global [%0], [%1], 16;" :: "r"(dst), "l"(src) : "memory")
#define CP_COMMIT() asm volatile("cp.async.commit_group;" ::: "memory")

__device__ __forceinline__ void mbar_wait(uint32_t mb, uint32_t parity) {
    uint32_t done;
    asm volatile(
        "{\n\t.reg .pred p;\n\t"
        "mbarrier.try_wait.parity.acquire.cta.shared::cta.b64 p, [%1], %2;\n\t"
        "selp.b32 %0, 1, 0, p;\n\t}"
        : "=r"(done) : "r"(mb), "r"(parity) : "memory");
    if (!done) {
        asm volatile(
            "{\n\t.reg .pred P1;\n\t"
            "W_%=:\n\t"
            "mbarrier.try_wait.parity.acquire.cta.shared::cta.b64 P1, [%0], %1, 0x989680;\n\t"
            "@P1 bra.uni D_%=;\n\t"
            "bra.uni W_%=;\n\t"
            "D_%=:\n\t}"
            :: "r"(mb), "r"(parity) : "memory");
    }
}

__device__ __forceinline__ void tcgen05_ld32x32(uint32_t* r, uint32_t addr) {
#if HAS_TCGEN05
    asm volatile(
        "tcgen05.ld.sync.aligned.32x32b.x32.b32 "
        "{%0,%1,%2,%3,%4,%5,%6,%7,%8,%9,%10,%11,%12,%13,%14,%15,"
        "%16,%17,%18,%19,%20,%21,%22,%23,%24,%25,%26,%27,%28,%29,%30,%31}, [%32];"
        : "=r"(r[0]), "=r"(r[1]), "=r"(r[2]), "=r"(r[3]), "=r"(r[4]), "=r"(r[5]), "=r"(r[6]), "=r"(r[7]),
          "=r"(r[8]), "=r"(r[9]), "=r"(r[10]), "=r"(r[11]), "=r"(r[12]), "=r"(r[13]), "=r"(r[14]), "=r"(r[15]),
          "=r"(r[16]), "=r"(r[17]), "=r"(r[18]), "=r"(r[19]), "=r"(r[20]), "=r"(r[21]), "=r"(r[22]), "=r"(r[23]),
          "=r"(r[24]), "=r"(r[25]), "=r"(r[26]), "=r"(r[27]), "=r"(r[28]), "=r"(r[29]), "=r"(r[30]), "=r"(r[31])
        : "r"(addr));
#else
    for (int i = 0; i < 32; i++) r[i] = 0;
#endif
}

__device__ __forceinline__ void mma_bf16_ss(uint32_t d, uint64_t a, uint64_t b,
                                            uint32_t idesc, uint32_t acc) {
#if HAS_TCGEN05
    uint32_t z = 0;
    asm volatile(
        "{\n\t.reg .pred p;\n\tsetp.ne.u32 p, %5, 0;\n\t"
        "tcgen05.mma.cta_group::1.kind::f16 [%0], %1, %2, %3, {%4,%4,%4,%4}, p;\n\t}"
        :: "r"(d), "l"(a), "l"(b), "r"(idesc), "r"(z), "r"(acc) : "memory");
#endif
}

// SW64 swizzle (atom = 8 rows x 64 B) + descriptor
__device__ __forceinline__ uint32_t swz64(uint32_t off) { return off ^ ((off >> 3) & 0x30); }
static constexpr uint64_t DESC_BASE_SW64 =
    (uint64_t(4) << 61) | (uint64_t(1) << 46) | (uint64_t(32) << 32) | (uint64_t(1) << 16);
__device__ __forceinline__ uint64_t mk_desc64(uint32_t addr) {
    return DESC_BASE_SW64 | ((uint64_t)(addr >> 4) & 0x3FFF);
}

// idesc: dtype=F32, atype=btype=BF16, M=128 (per MMA), N=256
#define MMA_IDESC ((1u << 4) | (1u << 7) | (1u << 10) | ((256u / 8) << 17) | ((128u / 16) << 24))

// ---------------- bf16 split --------------------------------------------------
__device__ __forceinline__ void split_bf16(float x, __nv_bfloat16& hi, __nv_bfloat16& lo) {
    hi = __float2bfloat16(x);
    lo = __float2bfloat16(x - __bfloat162float(hi));
}

// ---------------- cg1 tensor GEMM, 256x256 CTA tile ---------------------------
// Two 128x256 fp32 accumulators in TMEM (cols 0-255 / 256-511).
// bf16x3 split: Ahi*Bhi + Ahi*Blo + Alo*Bhi. KS=32, SW64 layout, 3 stages.
#define BMC 256                        // CTA M tile (2 x 128 accumulators)
#define BN  256
#define KS  32
#define NIT (DIM / KS)                 // 64
#define NSTAGE 3
#define OP_BYTES (256 * 64)            // 16 KB (256 rows x 64 B)
#define STAGE_BYTES (4 * OP_BYTES)     // 64 KB
#define SMEM_DATA 1024
#define SMEM_TOT (SMEM_DATA + NSTAGE * STAGE_BYTES)   // 197632 B
#define MB_DONE(s) (sb + 16 + (s) * 8)

// load one operand: 256 rows x 64 bytes (KS=32 bf16), SW64-swizzled
__device__ __forceinline__ void load_op256(uint32_t dst, const __nv_bfloat16* g,
                                           int k0, int tid) {
#pragma unroll
    for (int i = 0; i < 4; i++) {
        int idx = i * 256 + tid;       // 0..1023 chunks of 16 B
        int r = idx >> 2;
        int c = idx & 3;
        CP_ASYNC16(dst + swz64((uint32_t)(r * 64 + c * 16)),
                   g + (size_t)r * DIM + k0 + c * 8);
    }
}

__device__ __forceinline__ void load_stage(
    uint32_t sbase, int s, int k0,
    const __nv_bfloat16* Ah, const __nv_bfloat16* Al,
    const __nv_bfloat16* Bh, const __nv_bfloat16* Bl, int tid) {
    uint32_t st = sbase + SMEM_DATA + s * STAGE_BYTES;
    load_op256(st, Ah, k0, tid);
    load_op256(st + OP_BYTES, Al, k0, tid);
    load_op256(st + 2 * OP_BYTES, Bh, k0, tid);
    load_op256(st + 3 * OP_BYTES, Bl, k0, tid);
    CP_COMMIT();
}

template <int EPI>  // 0: tanh(+bias) -> bf16 hi/lo   1: +bias -> fp32
__global__ void __launch_bounds__(256, 1)
gemm_tc(const __nv_bfloat16* __restrict__ Ahi, const __nv_bfloat16* __restrict__ Alo,
        const __nv_bfloat16* __restrict__ Bhi, const __nv_bfloat16* __restrict__ Blo,
        const float* __restrict__ bias,
        __nv_bfloat16* __restrict__ Ohi, __nv_bfloat16* __restrict__ Olo,
        float* __restrict__ Of) {
    extern __shared__ char smem[];
    uint32_t sb = smem_u32(smem);
    const int tid = threadIdx.x;
    const int wid = tid >> 5;
    const int lid = tid & 31;
    const int bm = blockIdx.y * BMC;
    const int bn = blockIdx.x * BN;

    if (wid == 0) TCGEN05_ALLOC(sb, 512);
    if (tid == 0) {
#pragma unroll
        for (int s = 0; s < NSTAGE; s++) MBARRIER_INIT(MB_DONE(s), 1);
    }
    __syncthreads();
    uint32_t tmem;
    asm volatile("ld.shared.b32 %0, [%1];" : "=r"(tmem) : "r"(sb));
    if (wid == 0) TCGEN05_RELINQ();

    const __nv_bfloat16* Ah = Ahi + (size_t)bm * DIM;
    const __nv_bfloat16* Al = Alo + (size_t)bm * DIM;
    const __nv_bfloat16* Bh = Bhi + (size_t)bn * DIM;
    const __nv_bfloat16* Bl = Blo + (size_t)bn * DIM;

    load_stage(sb, 0, 0, Ah, Al, Bh, Bl, tid);
    load_stage(sb, 1, KS, Ah, Al, Bh, Bl, tid);
    load_stage(sb, 2, 2 * KS, Ah, Al, Bh, Bl, tid);

    for (int it = 0; it < NIT; it++) {
        const int s = it % NSTAGE;
        const uint32_t ph = (uint32_t)(it / NSTAGE) & 1u;
        if (it <= NIT - 3)      asm volatile("cp.async.wait_group 2;" ::: "memory");
        else if (it == NIT - 2) asm volatile("cp.async.wait_group 1;" ::: "memory");
        else                    asm volatile("cp.async.wait_group 0;" ::: "memory");
        __syncthreads();
        if (wid == 0 && elect_one()) {
            FENCE_PROXY_ASYNC();
            uint32_t st = sb + SMEM_DATA + s * STAGE_BYTES;
            uint64_t dAh = mk_desc64(st);
            uint64_t dAl = mk_desc64(st + OP_BYTES);
            uint64_t dBh = mk_desc64(st + 2 * OP_BYTES);
            uint64_t dBl = mk_desc64(st + 3 * OP_BYTES);
#pragma unroll
            for (int j = 0; j < 2; j++) {      // 2 K-steps of 16
#pragma unroll
                for (int m = 0; m < 2; m++) {  // two M-halves
                    uint64_t aoff = (uint64_t)(m * 512 + j * 2);  // m*8KB + j*32B (16B units)
                    uint32_t d = tmem + m * 256;
                    mma_bf16_ss(d, dAh + aoff, dBh + j * 2, MMA_IDESC, !(it == 0 && j == 0));
                    mma_bf16_ss(d, dAh + aoff, dBl + j * 2, MMA_IDESC, 1u);
                    mma_bf16_ss(d, dAl + aoff, dBh + j * 2, MMA_IDESC, 1u);
                }
            }
            TCGEN05_COMMIT(MB_DONE(s));
        }
        if (it + NSTAGE < NIT) {
            mbar_wait(MB_DONE(s), ph);   // MMA(it) done -> slot s reusable
            load_stage(sb, s, (it + NSTAGE) * KS, Ah, Al, Bh, Bl, tid);
        }
    }

    mbar_wait(MB_DONE((NIT - 1) % NSTAGE), (uint32_t)((NIT - 1) / NSTAGE) & 1u);
    TCGEN05_FENCE_AFTER();

    {
        const int acc = wid >> 2;                       // 0..1
        const int m = bm + acc * 128 + (wid & 3) * 32 + lid;
        const uint32_t tb = tmem + acc * 256;
#pragma unroll
        for (int cb = 0; cb < BN; cb += 32) {
            uint32_t r[32];
            tcgen05_ld32x32(r, tb + cb);
            TCGEN05_WAIT_LD();
            if (EPI == 0) {
#pragma unroll
                for (int c = 0; c < 32; c += 2) {
                    int n = bn + cb + c;
                    float f0 = __uint_as_float(r[c]) + bias[n];
                    float f1 = __uint_as_float(r[c + 1]) + bias[n + 1];
                    f0 = tanhf(f0); f1 = tanhf(f1);
                    __nv_bfloat16 h0, l0, h1, l1;
                    split_bf16(f0, h0, l0);
                    split_bf16(f1, h1, l1);
                    __nv_bfloat162 H; H.x = h0; H.y = h1;
                    __nv_bfloat162 L; L.x = l0; L.y = l1;
                    *(__nv_bfloat162*)(Ohi + (size_t)m * DIM + n) = H;
                    *(__nv_bfloat162*)(Olo + (size_t)m * DIM + n) = L;
                }
            } else {
#pragma unroll
                for (int c = 0; c < 32; c += 4) {
                    int n = bn + cb + c;
                    float4 v;
                    v.x = __uint_as_float(r[c + 0]) + bias[n + 0];
                    v.y = __uint_as_float(r[c + 1]) + bias[n + 1];
                    v.z = __uint_as_float(r[c + 2]) + bias[n + 2];
                    v.w = __uint_as_float(r[c + 3]) + bias[n + 3];
                    *(float4*)(Of + (size_t)m * DIM + n) = v;
                }
            }
        }
    }
    __syncthreads();
    if (tid == 0) {
#pragma unroll
        for (int s = 0; s < NSTAGE; s++) MBARRIER_INVAL(MB_DONE(s));
    }
    __syncthreads();
    if (wid == 0) TCGEN05_DEALLOC(tmem, 512);
}

// ---------------- block reduction of 4 sums ----------------------------------
__device__ __forceinline__ float4 block_reduce4(float4 v) {
    __shared__ float4 sh[8];
    int lane = threadIdx.x & 31;
    int w = threadIdx.x >> 5;
#pragma unroll
    for (int o = 16; o; o >>= 1) {
        v.x += __shfl_xor_sync(0xffffffffu, v.x, o);
        v.y += __shfl_xor_sync(0xffffffffu, v.y, o);
        v.z += __shfl_xor_sync(0xffffffffu, v.z, o);
        v.w += __shfl_xor_sync(0xffffffffu, v.w, o);
    }
    if (lane == 0) sh[w] = v;
    __syncthreads();
    if (w == 0) {
        float4 t = (lane < 8) ? sh[lane] : make_float4(0.f, 0.f, 0.f, 0.f);
#pragma unroll
        for (int o = 4; o; o >>= 1) {
            t.x += __shfl_xor_sync(0xffffffffu, t.x, o);
            t.y += __shfl_xor_sync(0xffffffffu, t.y, o);
            t.z += __shfl_xor_sync(0xffffffffu, t.z, o);
            t.w += __shfl_xor_sync(0xffffffffu, t.w, o);
        }
        if (lane == 0) sh[0] = t;
    }
    __syncthreads();
    return sh[0];
}

__device__ __forceinline__ void write_coefs(int row, float nh2,
                                            float de, float dc, float dn) {
    float nh = sqrtf(nh2);
    float inv = 1.f / fmaxf(nh, 1e-12f);
    float dots[3] = {de, dc, dn};
#pragma unroll
    for (int k = 0; k < 3; k++) {
        float a = dots[k] * inv;
        float r = sqrtf(fmaxf(nh2 - 2.f * dots[k] + 1.f, 0.f));
        g_coef[(size_t)row * 4 + k] = kS[k] * (DIVC - a) / fmaxf(r, 1e-12f);
    }
}

// ---------------- small prep kernels ------------------------------------------
__global__ void prep_dirs_kernel(const float* __restrict__ e,
                                 const float* __restrict__ c,
                                 const float* __restrict__ n) {
    const float* src = (blockIdx.x == 0) ? e : (blockIdx.x == 1 ? c : n);
    float4 s = make_float4(0.f, 0.f, 0.f, 0.f);
    for (int i = threadIdx.x; i < DIM; i += 256) {
        float v = src[i];
        s.x += v * v;
    }
    s = block_reduce4(s);
    float inv = 1.f / fmaxf(sqrtf(s.x), 1e-12f);
    for (int i = threadIdx.x; i < DIM; i += 256)
        g_dirs[blockIdx.x * DIM + i] = src[i] * inv;
}

// fused: split h0 into hi/lo + compute layer-0 stats/coefs
__global__ void init_kernel(const float* __restrict__ h0,
                            __nv_bfloat16* __restrict__ hhi,
                            __nv_bfloat16* __restrict__ hlo) {
    int row = blockIdx.x;
    int t = threadIdx.x;
    const float* hr = h0 + (size_t)row * DIM;
    float4 s = make_float4(0.f, 0.f, 0.f, 0.f);
#pragma unroll
    for (int j = 0; j < DIM / 256; j++) {
        int i = t + j * 256;
        float v = hr[i];
        s.x += v * v;
        s.y += v * g_dirs[i];
        s.z += v * g_dirs[DIM + i];
        s.w += v * g_dirs[2 * DIM + i];
        __nv_bfloat16 hi, lo;
        split_bf16(v, hi, lo);
        hhi[(size_t)row * DIM + i] = hi;
        hlo[(size_t)row * DIM + i] = lo;
    }
    s = block_reduce4(s);
    if (t == 0) write_coefs(row, s.x, s.y, s.z, s.w);
}

__global__ void conv_split_kernel(const float* __restrict__ src,
                                  __nv_bfloat16* __restrict__ hi,
                                  __nv_bfloat16* __restrict__ lo, size_t n) {
    size_t i = (size_t)blockIdx.x * blockDim.x + threadIdx.x;
    if (i < n) {
        __nv_bfloat16 h, l;
        split_bf16(src[i], h, l);
        hi[i] = h;
        lo[i] = l;
    }
}

// ---------------- fused update + cap + stats + bf16 split ---------------------
__global__ void update_kernel(__nv_bfloat16* __restrict__ hhi,
                              __nv_bfloat16* __restrict__ hlo,
                              const float* __restrict__ delta,
                              float* __restrict__ hout, int write_f32) {
    int row = blockIdx.x;
    int t = threadIdx.x;
    const float* dr = delta + (size_t)row * DIM;

    float ce = g_coef[(size_t)row * 4 + 0];
    float cc = g_coef[(size_t)row * 4 + 1];
    float cn = g_coef[(size_t)row * 4 + 2];
    float keep = 1.f - (ce + cc + cn);

    const int EPT = DIM / 256;
    float x[EPT];
    float4 s = make_float4(0.f, 0.f, 0.f, 0.f);
#pragma unroll
    for (int j = 0; j < EPT; j++) {
        int i = t + j * 256;
        float ed = g_dirs[i];
        float cd = g_dirs[DIM + i];
        float nd = g_dirs[2 * DIM + i];
        float hv = __bfloat162float(hhi[(size_t)row * DIM + i]) +
                   __bfloat162float(hlo[(size_t)row * DIM + i]);
        float v = hv * keep + dr[i] + ce * ed + cc * cd + cn * nd;
        x[j] = v;
        s.x += v * v;
        s.y += v * ed;
        s.z += v * cd;
        s.w += v * nd;
    }
    s = block_reduce4(s);
    float norm = sqrtf(s.x);
    float sc = (norm > CAPV) ? (CAPV / (norm + 1e-8f)) : 1.f;
#pragma unroll
    for (int j = 0; j < EPT; j++) {
        int i = t + j * 256;
        float v = x[j] * sc;
        __nv_bfloat16 hi, lo;
        split_bf16(v, hi, lo);
        hhi[(size_t)row * DIM + i] = hi;
        hlo[(size_t)row * DIM + i] = lo;
        if (write_f32) hout[(size_t)row * DIM + i] = v;
    }
    if (t == 0)
        write_coefs(row, sc * sc * s.x, sc * s.y, sc * s.z, sc * s.w);
}

// ---------------- launch --------------------------------------------------------
extern "C" void kernel_launch(void* const* d_in, const int* in_sizes, int n_in,
                              void* d_out, int out_size) {
    const float* h0 = (const float*)d_in[0];
    const float* ae = (const float*)d_in[1];
    const float* ac = (const float*)d_in[2];
    const float* an = (const float*)d_in[3];
    const float* W1 = (const float*)d_in[4];
    const float* b1 = (const float*)d_in[5];
    const float* W2 = (const float*)d_in[6];
    const float* b2 = (const float*)d_in[7];
    float* h = (float*)d_out;

    float* Dptr;           cudaGetSymbolAddress((void**)&Dptr, g_D);
    __nv_bfloat16 *hhi, *hlo, *Thi, *Tlo, *W1h, *W1l, *W2h, *W2l;
    cudaGetSymbolAddress((void**)&hhi, g_hhi);
    cudaGetSymbolAddress((void**)&hlo, g_hlo);
    cudaGetSymbolAddress((void**)&Thi, g_Thi);
    cudaGetSymbolAddress((void**)&Tlo, g_Tlo);
    cudaGetSymbolAddress((void**)&W1h, g_W1hi);
    cudaGetSymbolAddress((void**)&W1l, g_W1lo);
    cudaGetSymbolAddress((void**)&W2h, g_W2hi);
    cudaGetSymbolAddress((void**)&W2l, g_W2lo);

    cudaFuncSetAttribute(gemm_tc<0>, cudaFuncAttributeMaxDynamicSharedMemorySize, SMEM_TOT);
    cudaFuncSetAttribute(gemm_tc<1>, cudaFuncAttributeMaxDynamicSharedMemorySize, SMEM_TOT);

    size_t nw = (size_t)DIM * DIM;
    conv_split_kernel<<<(unsigned)((nw + 1023) / 1024), 1024>>>(W1, W1h, W1l, nw);
    conv_split_kernel<<<(unsigned)((nw + 1023) / 1024), 1024>>>(W2, W2h, W2l, nw);
    prep_dirs_kernel<<<3, 256>>>(ae, ac, an);
    init_kernel<<<BATCH, 256>>>(h0, hhi, hlo);

    dim3 ggrid(DIM / BN, BATCH / BMC);   // (8, 64) = 512 CTAs
    for (int l = 0; l < NLAYERS; l++) {
        gemm_tc<0><<<ggrid, 256, SMEM_TOT>>>(hhi, hlo, W1h, W1l, b1, Thi, Tlo, nullptr);
        gemm_tc<1><<<ggrid, 256, SMEM_TOT>>>(Thi, Tlo, W2h, W2l, b2, nullptr, nullptr, Dptr);
        update_kernel<<<BATCH, 256>>>(hhi, hlo, Dptr, h, l == NLAYERS - 1);
    }
}

// round 10
// speedup vs baseline: 1.4053x; 1.4053x over previous
#include <cuda_runtime.h>
#include <cuda_bf16.h>
#include <math.h>
#include <stdint.h>

#define DIM    2048
#define BATCH  16384
#define NLAYERS 4

static __device__ __constant__ float kS[3] = {0.1f, 0.1f, 0.05f};
#define DIVC 0.38f
#define CAPV 10.0f

// tcgen05 is an arch-accelerated feature: only emit its PTX in the sm_10Xa pass.
#if defined(__CUDA_ARCH_FEAT_SM103_ALL) || defined(__CUDA_ARCH_FEAT_SM100_ALL) || defined(__CUDA_ARCH_FEAT_SM101_ALL)
#define HAS_TCGEN05 1
#else
#define HAS_TCGEN05 0
#endif

// ---------------- scratch (static device globals; no allocation) -------------
__device__ __nv_bfloat16 g_hhi[(size_t)BATCH * DIM];
__device__ __nv_bfloat16 g_hlo[(size_t)BATCH * DIM];
__device__ __nv_bfloat16 g_Thi[(size_t)BATCH * DIM];
__device__ __nv_bfloat16 g_Tlo[(size_t)BATCH * DIM];
__device__ __nv_bfloat16 g_W1hi[(size_t)DIM * DIM];
__device__ __nv_bfloat16 g_W1lo[(size_t)DIM * DIM];
__device__ __nv_bfloat16 g_W2hi[(size_t)DIM * DIM];
__device__ __nv_bfloat16 g_W2lo[(size_t)DIM * DIM];
__device__ float g_D[(size_t)BATCH * DIM];
__device__ float g_dirs[3 * DIM];
__device__ float g_coef[(size_t)BATCH * 4];

// ---------------- PTX helpers -------------------------------------------------
__device__ __forceinline__ uint32_t smem_u32(const void* p) {
    uint32_t a;
    asm("{ .reg .u64 t; cvta.to.shared.u64 t, %1; cvt.u32.u64 %0, t; }" : "=r"(a) : "l"(p));
    return a;
}

#if HAS_TCGEN05
#define TCGEN05_ALLOC(sm, n) \
    asm volatile("tcgen05.alloc.cta_group::1.sync.aligned.shared::cta.b32 [%0], %1;" :: "r"(sm), "r"(n) : "memory")
#define TCGEN05_RELINQ() \
    asm volatile("tcgen05.relinquish_alloc_permit.cta_group::1.sync.aligned;")
#define TCGEN05_DEALLOC(t, n) \
    asm volatile("tcgen05.dealloc.cta_group::1.sync.aligned.b32 %0, %1;" :: "r"(t), "r"(n))
#define TCGEN05_COMMIT(mb) \
    asm volatile("tcgen05.commit.cta_group::1.mbarrier::arrive::one.shared::cluster.b64 [%0];" :: "r"(mb) : "memory")
#define TCGEN05_FENCE_AFTER() asm volatile("tcgen05.fence::after_thread_sync;" ::: "memory")
#define TCGEN05_WAIT_LD() asm volatile("tcgen05.wait::ld.sync.aligned;" ::: "memory")
#else
#define TCGEN05_ALLOC(sm, n)   ((void)0)
#define TCGEN05_RELINQ()       ((void)0)
#define TCGEN05_DEALLOC(t, n)  ((void)0)
#define TCGEN05_COMMIT(mb)     ((void)0)
#define TCGEN05_FENCE_AFTER()  ((void)0)
#define TCGEN05_WAIT_LD()      ((void)0)
#endif

#define MBARRIER_INIT(mb, c) \
    asm volatile("mbarrier.init.shared.b64 [%0], %1;" :: "r"(mb), "r"(c) : "memory")
#define MBARRIER_INVAL(mb) \
    asm volatile("mbarrier.inval.shared.b64 [%0];" :: "r"(mb) : "memory")
#define FENCE_PROXY_ASYNC() asm volatile("fence.proxy.async.shared::cta;" ::: "memory")
#define CP_ASYNC16(dst, src) \
    asm volatile("cp.async.cg.shared.global [%0], [%1], 16;" :: "r"(dst), "l"(src) : "memory")
// arrive-on-complete WITHOUT incrementing expected count (init count carries it)
#define CP_ASYNC_MBAR_ARRIVE(mb) \
    asm volatile("cp.async.mbarrier.arrive.noinc.shared::cta.b64 [%0];" :: "r"(mb) : "memory")

__device__ __forceinline__ void mbar_wait(uint32_t mb, uint32_t parity) {
    uint32_t done;
    asm volatile(
        "{\n\t.reg .pred p;\n\t"
        "mbarrier.try_wait.parity.acquire.cta.shared::cta.b64 p, [%1], %2;\n\t"
        "selp.b32 %0, 1, 0, p;\n\t}"
        : "=r"(done) : "r"(mb), "r"(parity) : "memory");
    if (!done) {
        asm volatile(
            "{\n\t.reg .pred P1;\n\t"
            "W_%=:\n\t"
            "mbarrier.try_wait.parity.acquire.cta.shared::cta.b64 P1, [%0], %1, 0x989680;\n\t"
            "@P1 bra.uni D_%=;\n\t"
            "bra.uni W_%=;\n\t"
            "D_%=:\n\t}"
            :: "r"(mb), "r"(parity) : "memory");
    }
}

__device__ __forceinline__ void tcgen05_ld32x32(uint32_t* r, uint32_t addr) {
#if HAS_TCGEN05
    asm volatile(
        "tcgen05.ld.sync.aligned.32x32b.x32.b32 "
        "{%0,%1,%2,%3,%4,%5,%6,%7,%8,%9,%10,%11,%12,%13,%14,%15,"
        "%16,%17,%18,%19,%20,%21,%22,%23,%24,%25,%26,%27,%28,%29,%30,%31}, [%32];"
        : "=r"(r[0]), "=r"(r[1]), "=r"(r[2]), "=r"(r[3]), "=r"(r[4]), "=r"(r[5]), "=r"(r[6]), "=r"(r[7]),
          "=r"(r[8]), "=r"(r[9]), "=r"(r[10]), "=r"(r[11]), "=r"(r[12]), "=r"(r[13]), "=r"(r[14]), "=r"(r[15]),
          "=r"(r[16]), "=r"(r[17]), "=r"(r[18]), "=r"(r[19]), "=r"(r[20]), "=r"(r[21]), "=r"(r[22]), "=r"(r[23]),
          "=r"(r[24]), "=r"(r[25]), "=r"(r[26]), "=r"(r[27]), "=r"(r[28]), "=r"(r[29]), "=r"(r[30]), "=r"(r[31])
        : "r"(addr));
#else
    for (int i = 0; i < 32; i++) r[i] = 0;
#endif
}

__device__ __forceinline__ void mma_bf16_ss(uint32_t d, uint64_t a, uint64_t b,
                                            uint32_t idesc, uint32_t acc) {
#if HAS_TCGEN05
    uint32_t z = 0;
    asm volatile(
        "{\n\t.reg .pred p;\n\tsetp.ne.u32 p, %5, 0;\n\t"
        "tcgen05.mma.cta_group::1.kind::f16 [%0], %1, %2, %3, {%4,%4,%4,%4}, p;\n\t}"
        :: "r"(d), "l"(a), "l"(b), "r"(idesc), "r"(z), "r"(acc) : "memory");
#endif
}

// SW64 swizzle (atom = 8 rows x 64 B) + descriptor  (proven correct in R7)
__device__ __forceinline__ uint32_t swz64(uint32_t off) { return off ^ ((off >> 3) & 0x30); }
static constexpr uint64_t DESC_BASE_SW64 =
    (uint64_t(4) << 61) | (uint64_t(1) << 46) | (uint64_t(32) << 32) | (uint64_t(1) << 16);
__device__ __forceinline__ uint64_t mk_desc64(uint32_t addr) {
    return DESC_BASE_SW64 | ((uint64_t)(addr >> 4) & 0x3FFF);
}

// idesc: dtype=F32, atype=btype=BF16, M=128 (per MMA), N=256
#define MMA_IDESC ((1u << 4) | (1u << 7) | (1u << 10) | ((256u / 8) << 17) | ((128u / 16) << 24))

// ---------------- bf16 split --------------------------------------------------
__device__ __forceinline__ void split_bf16(float x, __nv_bfloat16& hi, __nv_bfloat16& lo) {
    hi = __float2bfloat16(x);
    lo = __float2bfloat16(x - __bfloat162float(hi));
}

// ---------------- cg1 tensor GEMM, 256x256 CTA tile, warp-specialized ---------
// Two 128x256 fp32 accumulators in TMEM (cols 0-255 / 256-511).
// bf16x3 split: Ahi*Bhi + Ahi*Blo + Alo*Bhi. KS=32, SW64, 3 stages.
// Warps 4-7 = cp.async producers (noinc arrive-on-complete);
// tid 0 = MMA issuer; NO per-iteration __syncthreads.
// IMPORTANT (R9 lesson): mbarrier parity waits alias every 2 phases — only
// threads that consumed every intermediate phase may wait the final one.
// Loaders (phase-exact on done[]) perform the final wait; __syncthreads
// releases the rest of the CTA into the epilogue.
#define BMC 256
#define BN  256
#define KS  32
#define NIT (DIM / KS)                 // 64
#define NSTAGE 3
#define OP_BYTES (256 * 64)            // 16 KB
#define STAGE_BYTES (4 * OP_BYTES)     // 64 KB
#define SMEM_DATA 1024
#define SMEM_TOT (SMEM_DATA + NSTAGE * STAGE_BYTES)   // 197632 B
#define MB_FULL(s) (sb + 16 + (s) * 8)
#define MB_DONE(s) (sb + 48 + (s) * 8)
#define NLOAD 128                      // loader threads (warps 4-7)

// one operand slice: 256 rows x 64 B; ltid in [0,128), 8 chunks of 16 B each
__device__ __forceinline__ void load_op256_w(uint32_t dst, const __nv_bfloat16* g,
                                             int k0, int ltid) {
#pragma unroll
    for (int i = 0; i < 8; i++) {
        int idx = i * NLOAD + ltid;    // 0..1023
        int r = idx >> 2;
        int c = idx & 3;
        CP_ASYNC16(dst + swz64((uint32_t)(r * 64 + c * 16)),
                   g + (size_t)r * DIM + k0 + c * 8);
    }
}

__device__ __forceinline__ void load_stage_w(
    uint32_t sbase, int s, int k0,
    const __nv_bfloat16* Ah, const __nv_bfloat16* Al,
    const __nv_bfloat16* Bh, const __nv_bfloat16* Bl, int ltid) {
    uint32_t st = sbase + SMEM_DATA + s * STAGE_BYTES;
    load_op256_w(st, Ah, k0, ltid);
    load_op256_w(st + OP_BYTES, Al, k0, ltid);
    load_op256_w(st + 2 * OP_BYTES, Bh, k0, ltid);
    load_op256_w(st + 3 * OP_BYTES, Bl, k0, ltid);
}

template <int EPI>  // 0: tanh(+bias) -> bf16 hi/lo   1: +bias -> fp32
__global__ void __launch_bounds__(256, 1)
gemm_tc(const __nv_bfloat16* __restrict__ Ahi, const __nv_bfloat16* __restrict__ Alo,
        const __nv_bfloat16* __restrict__ Bhi, const __nv_bfloat16* __restrict__ Blo,
        const float* __restrict__ bias,
        __nv_bfloat16* __restrict__ Ohi, __nv_bfloat16* __restrict__ Olo,
        float* __restrict__ Of) {
    extern __shared__ char smem[];
    uint32_t sb = smem_u32(smem);
    const int tid = threadIdx.x;
    const int wid = tid >> 5;
    const int lid = tid & 31;
    const int bm = blockIdx.y * BMC;
    const int bn = blockIdx.x * BN;

    if (wid == 0) TCGEN05_ALLOC(sb, 512);
    if (tid == 0) {
#pragma unroll
        for (int s = 0; s < NSTAGE; s++) {
            MBARRIER_INIT(MB_FULL(s), NLOAD);  // one noinc arrive per loader thread
            MBARRIER_INIT(MB_DONE(s), 1);      // tcgen05 commit
        }
    }
    __syncthreads();
    uint32_t tmem;
    asm volatile("ld.shared.b32 %0, [%1];" : "=r"(tmem) : "r"(sb));
    if (wid == 0) TCGEN05_RELINQ();
    __syncthreads();   // barriers + tmem visible before producers start

    const __nv_bfloat16* Ah = Ahi + (size_t)bm * DIM;
    const __nv_bfloat16* Al = Alo + (size_t)bm * DIM;
    const __nv_bfloat16* Bh = Bhi + (size_t)bn * DIM;
    const __nv_bfloat16* Bl = Blo + (size_t)bn * DIM;

    const bool is_loader = (tid >= 128);
    const int ltid = tid - 128;

    if (is_loader) {
        // prologue: fill all 3 stages (no done-wait on first use)
#pragma unroll
        for (int s = 0; s < NSTAGE; s++) {
            load_stage_w(sb, s, s * KS, Ah, Al, Bh, Bl, ltid);
            CP_ASYNC_MBAR_ARRIVE(MB_FULL(s));
        }
        for (int it = 0; it + NSTAGE < NIT; it++) {
            const int s = it % NSTAGE;
            const uint32_t ph = (uint32_t)(it / NSTAGE) & 1u;
            mbar_wait(MB_DONE(s), ph);            // MMA(it) done -> slot reusable
            load_stage_w(sb, s, (it + NSTAGE) * KS, Ah, Al, Bh, Bl, ltid);
            CP_ASYNC_MBAR_ARRIVE(MB_FULL(s));
        }
        // final MMA completion: loaders are the ONLY threads with exact phase
        // tracking on done[] (they consumed every prior phase in order), so
        // only they may issue this parity wait without aliasing.
        mbar_wait(MB_DONE((NIT - 1) % NSTAGE), (uint32_t)((NIT - 1) / NSTAGE) & 1u);
    } else if (tid == 0) {
        // MMA issuer
        for (int it = 0; it < NIT; it++) {
            const int s = it % NSTAGE;
            const uint32_t ph = (uint32_t)(it / NSTAGE) & 1u;
            mbar_wait(MB_FULL(s), ph);            // stage data complete
            FENCE_PROXY_ASYNC();
            uint32_t st = sb + SMEM_DATA + s * STAGE_BYTES;
            uint64_t dAh = mk_desc64(st);
            uint64_t dAl = mk_desc64(st + OP_BYTES);
            uint64_t dBh = mk_desc64(st + 2 * OP_BYTES);
            uint64_t dBl = mk_desc64(st + 3 * OP_BYTES);
#pragma unroll
            for (int j = 0; j < 2; j++) {         // 2 K-steps of 16
#pragma unroll
                for (int m = 0; m < 2; m++) {     // two M-halves
                    uint64_t aoff = (uint64_t)(m * 512 + j * 2);
                    uint32_t d = tmem + m * 256;
                    mma_bf16_ss(d, dAh + aoff, dBh + j * 2, MMA_IDESC, !(it == 0 && j == 0));
                    mma_bf16_ss(d, dAh + aoff, dBl + j * 2, MMA_IDESC, 1u);
                    mma_bf16_ss(d, dAl + aoff, dBh + j * 2, MMA_IDESC, 1u);
                }
            }
            TCGEN05_COMMIT(MB_DONE(s));
        }
    }

    // release the whole CTA only after loaders observed the final commit
    __syncthreads();
    TCGEN05_FENCE_AFTER();

    {
        const int acc = wid >> 2;                       // 0..1
        const int m = bm + acc * 128 + (wid & 3) * 32 + lid;
        const uint32_t tb = tmem + acc * 256;
#pragma unroll
        for (int cb = 0; cb < BN; cb += 32) {
            uint32_t r[32];
            tcgen05_ld32x32(r, tb + cb);
            TCGEN05_WAIT_LD();
            if (EPI == 0) {
#pragma unroll
                for (int c = 0; c < 32; c += 2) {
                    int n = bn + cb + c;
                    float f0 = __uint_as_float(r[c]) + bias[n];
                    float f1 = __uint_as_float(r[c + 1]) + bias[n + 1];
                    f0 = tanhf(f0); f1 = tanhf(f1);
                    __nv_bfloat16 h0, l0, h1, l1;
                    split_bf16(f0, h0, l0);
                    split_bf16(f1, h1, l1);
                    __nv_bfloat162 H; H.x = h0; H.y = h1;
                    __nv_bfloat162 L; L.x = l0; L.y = l1;
                    *(__nv_bfloat162*)(Ohi + (size_t)m * DIM + n) = H;
                    *(__nv_bfloat162*)(Olo + (size_t)m * DIM + n) = L;
                }
            } else {
#pragma unroll
                for (int c = 0; c < 32; c += 4) {
                    int n = bn + cb + c;
                    float4 v;
                    v.x = __uint_as_float(r[c + 0]) + bias[n + 0];
                    v.y = __uint_as_float(r[c + 1]) + bias[n + 1];
                    v.z = __uint_as_float(r[c + 2]) + bias[n + 2];
                    v.w = __uint_as_float(r[c + 3]) + bias[n + 3];
                    *(float4*)(Of + (size_t)m * DIM + n) = v;
                }
            }
        }
    }
    __syncthreads();
    if (tid == 0) {
#pragma unroll
        for (int s = 0; s < NSTAGE; s++) { MBARRIER_INVAL(MB_FULL(s)); MBARRIER_INVAL(MB_DONE(s)); }
    }
    __syncthreads();
    if (wid == 0) TCGEN05_DEALLOC(tmem, 512);
}

// ---------------- block reduction of 4 sums ----------------------------------
__device__ __forceinline__ float4 block_reduce4(float4 v) {
    __shared__ float4 sh[8];
    int lane = threadIdx.x & 31;
    int w = threadIdx.x >> 5;
#pragma unroll
    for (int o = 16; o; o >>= 1) {
        v.x += __shfl_xor_sync(0xffffffffu, v.x, o);
        v.y += __shfl_xor_sync(0xffffffffu, v.y, o);
        v.z += __shfl_xor_sync(0xffffffffu, v.z, o);
        v.w += __shfl_xor_sync(0xffffffffu, v.w, o);
    }
    if (lane == 0) sh[w] = v;
    __syncthreads();
    if (w == 0) {
        float4 t = (lane < 8) ? sh[lane] : make_float4(0.f, 0.f, 0.f, 0.f);
#pragma unroll
        for (int o = 4; o; o >>= 1) {
            t.x += __shfl_xor_sync(0xffffffffu, t.x, o);
            t.y += __shfl_xor_sync(0xffffffffu, t.y, o);
            t.z += __shfl_xor_sync(0xffffffffu, t.z, o);
            t.w += __shfl_xor_sync(0xffffffffu, t.w, o);
        }
        if (lane == 0) sh[0] = t;
    }
    __syncthreads();
    return sh[0];
}

__device__ __forceinline__ void write_coefs(int row, float nh2,
                                            float de, float dc, float dn) {
    float nh = sqrtf(nh2);
    float inv = 1.f / fmaxf(nh, 1e-12f);
    float dots[3] = {de, dc, dn};
#pragma unroll
    for (int k = 0; k < 3; k++) {
        float a = dots[k] * inv;
        float r = sqrtf(fmaxf(nh2 - 2.f * dots[k] + 1.f, 0.f));
        g_coef[(size_t)row * 4 + k] = kS[k] * (DIVC - a) / fmaxf(r, 1e-12f);
    }
}

// ---------------- small prep kernels ------------------------------------------
__global__ void prep_dirs_kernel(const float* __restrict__ e,
                                 const float* __restrict__ c,
                                 const float* __restrict__ n) {
    const float* src = (blockIdx.x == 0) ? e : (blockIdx.x == 1 ? c : n);
    float4 s = make_float4(0.f, 0.f, 0.f, 0.f);
    for (int i = threadIdx.x; i < DIM; i += 256) {
        float v = src[i];
        s.x += v * v;
    }
    s = block_reduce4(s);
    float inv = 1.f / fmaxf(sqrtf(s.x), 1e-12f);
    for (int i = threadIdx.x; i < DIM; i += 256)
        g_dirs[blockIdx.x * DIM + i] = src[i] * inv;
}

// fused: split h0 into hi/lo + compute layer-0 stats/coefs
__global__ void init_kernel(const float* __restrict__ h0,
                            __nv_bfloat16* __restrict__ hhi,
                            __nv_bfloat16* __restrict__ hlo) {
    int row = blockIdx.x;
    int t = threadIdx.x;
    const float* hr = h0 + (size_t)row * DIM;
    float4 s = make_float4(0.f, 0.f, 0.f, 0.f);
#pragma unroll
    for (int j = 0; j < DIM / 256; j++) {
        int i = t + j * 256;
        float v = hr[i];
        s.x += v * v;
        s.y += v * g_dirs[i];
        s.z += v * g_dirs[DIM + i];
        s.w += v * g_dirs[2 * DIM + i];
        __nv_bfloat16 hi, lo;
        split_bf16(v, hi, lo);
        hhi[(size_t)row * DIM + i] = hi;
        hlo[(size_t)row * DIM + i] = lo;
    }
    s = block_reduce4(s);
    if (t == 0) write_coefs(row, s.x, s.y, s.z, s.w);
}

__global__ void conv_split_kernel(const float* __restrict__ src,
                                  __nv_bfloat16* __restrict__ hi,
                                  __nv_bfloat16* __restrict__ lo, size_t n) {
    size_t i = (size_t)blockIdx.x * blockDim.x + threadIdx.x;
    if (i < n) {
        __nv_bfloat16 h, l;
        split_bf16(src[i], h, l);
        hi[i] = h;
        lo[i] = l;
    }
}

// ---------------- fused update + cap + stats + bf16 split ---------------------
__global__ void update_kernel(__nv_bfloat16* __restrict__ hhi,
                              __nv_bfloat16* __restrict__ hlo,
                              const float* __restrict__ delta,
                              float* __restrict__ hout, int write_f32) {
    int row = blockIdx.x;
    int t = threadIdx.x;
    const float* dr = delta + (size_t)row * DIM;

    float ce = g_coef[(size_t)row * 4 + 0];
    float cc = g_coef[(size_t)row * 4 + 1];
    float cn = g_coef[(size_t)row * 4 + 2];
    float keep = 1.f - (ce + cc + cn);

    const int EPT = DIM / 256;
    float x[EPT];
    float4 s = make_float4(0.f, 0.f, 0.f, 0.f);
#pragma unroll
    for (int j = 0; j < EPT; j++) {
        int i = t + j * 256;
        float ed = g_dirs[i];
        float cd = g_dirs[DIM + i];
        float nd = g_dirs[2 * DIM + i];
        float hv = __bfloat162float(hhi[(size_t)row * DIM + i]) +
                   __bfloat162float(hlo[(size_t)row * DIM + i]);
        float v = hv * keep + dr[i] + ce * ed + cc * cd + cn * nd;
        x[j] = v;
        s.x += v * v;
        s.y += v * ed;
        s.z += v * cd;
        s.w += v * nd;
    }
    s = block_reduce4(s);
    float norm = sqrtf(s.x);
    float sc = (norm > CAPV) ? (CAPV / (norm + 1e-8f)) : 1.f;
#pragma unroll
    for (int j = 0; j < EPT; j++) {
        int i = t + j * 256;
        float v = x[j] * sc;
        __nv_bfloat16 hi, lo;
        split_bf16(v, hi, lo);
        hhi[(size_t)row * DIM + i] = hi;
        hlo[(size_t)row * DIM + i] = lo;
        if (write_f32) hout[(size_t)row * DIM + i] = v;
    }
    if (t == 0)
        write_coefs(row, sc * sc * s.x, sc * s.y, sc * s.z, sc * s.w);
}

// ---------------- launch --------------------------------------------------------
extern "C" void kernel_launch(void* const* d_in, const int* in_sizes, int n_in,
                              void* d_out, int out_size) {
    const float* h0 = (const float*)d_in[0];
    const float* ae = (const float*)d_in[1];
    const float* ac = (const float*)d_in[2];
    const float* an = (const float*)d_in[3];
    const float* W1 = (const float*)d_in[4];
    const float* b1 = (const float*)d_in[5];
    const float* W2 = (const float*)d_in[6];
    const float* b2 = (const float*)d_in[7];
    float* h = (float*)d_out;

    float* Dptr;           cudaGetSymbolAddress((void**)&Dptr, g_D);
    __nv_bfloat16 *hhi, *hlo, *Thi, *Tlo, *W1h, *W1l, *W2h, *W2l;
    cudaGetSymbolAddress((void**)&hhi, g_hhi);
    cudaGetSymbolAddress((void**)&hlo, g_hlo);
    cudaGetSymbolAddress((void**)&Thi, g_Thi);
    cudaGetSymbolAddress((void**)&Tlo, g_Tlo);
    cudaGetSymbolAddress((void**)&W1h, g_W1hi);
    cudaGetSymbolAddress((void**)&W1l, g_W1lo);
    cudaGetSymbolAddress((void**)&W2h, g_W2hi);
    cudaGetSymbolAddress((void**)&W2l, g_W2lo);

    cudaFuncSetAttribute(gemm_tc<0>, cudaFuncAttributeMaxDynamicSharedMemorySize, SMEM_TOT);
    cudaFuncSetAttribute(gemm_tc<1>, cudaFuncAttributeMaxDynamicSharedMemorySize, SMEM_TOT);

    size_t nw = (size_t)DIM * DIM;
    conv_split_kernel<<<(unsigned)((nw + 1023) / 1024), 1024>>>(W1, W1h, W1l, nw);
    conv_split_kernel<<<(unsigned)((nw + 1023) / 1024), 1024>>>(W2, W2h, W2l, nw);
    prep_dirs_kernel<<<3, 256>>>(ae, ac, an);
    init_kernel<<<BATCH, 256>>>(h0, hhi, hlo);

    dim3 ggrid(DIM / BN, BATCH / BMC);   // (8, 64) = 512 CTAs
    for (int l = 0; l < NLAYERS; l++) {
        gemm_tc<0><<<ggrid, 256, SMEM_TOT>>>(hhi, hlo, W1h, W1l, b1, Thi, Tlo, nullptr);
        gemm_tc<1><<<ggrid, 256, SMEM_TOT>>>(Thi, Tlo, W2h, W2l, b2, nullptr, nullptr, Dptr);
        update_kernel<<<BATCH, 256>>>(hhi, hlo, Dptr, h, l == NLAYERS - 1);
    }
}